// round 1
// baseline (speedup 1.0000x reference)
#include <cuda_runtime.h>
#include <math.h>

#define N_MAX 32768
#define F_MAX 256

// ---------------- scratch (device globals: no allocation allowed) ----------------
__device__ float g_bufA[N_MAX * F_MAX];   // layer input (normalized output of prev)
__device__ float g_bufH[N_MAX * F_MAX];   // GEMM output
__device__ float g_bufG[N_MAX * F_MAX];   // aggregation output
__device__ float g_dinv[N_MAX];           // degree -> deg^-1/2
__device__ float g_sum[F_MAX];
__device__ float g_sumsq[F_MAX];
__device__ float g_mu[F_MAX];
__device__ float g_istd[F_MAX];
__device__ int   g_i64;                   // 1 if edge_index is int64, 0 if int32

// ---------------- edge_index dtype detection ----------------
// If int64 (little-endian, values < 2^31), every odd int32 word is 0.
__global__ void k_detect(const int* __restrict__ ei) {
    if (threadIdx.x == 0 && blockIdx.x == 0) {
        int z = 1;
        for (int i = 0; i < 32; i++)
            if (ei[2 * i + 1] != 0) z = 0;
        g_i64 = z;
    }
}

__device__ __forceinline__ void edge_sd(const void* ei, int e, int E, int& s, int& d) {
    if (g_i64) {
        const long long* p = (const long long*)ei;
        s = (int)p[e];
        d = (int)p[(long long)E + e];
    } else {
        const int* p = (const int*)ei;
        s = p[e];
        d = p[E + e];
    }
}

// ---------------- degree / normalization ----------------
__global__ void k_deg_init(int N) {
    int i = blockIdx.x * blockDim.x + threadIdx.x;
    if (i < N) g_dinv[i] = 1.0f;   // self-loop
}

__global__ void k_deg(const void* __restrict__ ei, int E) {
    int stride = gridDim.x * blockDim.x;
    for (int e = blockIdx.x * blockDim.x + threadIdx.x; e < E; e += stride) {
        int s, d;
        edge_sd(ei, e, E, s, d);
        atomicAdd(&g_dinv[d], 1.0f);
    }
}

__global__ void k_dinv(int N) {
    int i = blockIdx.x * blockDim.x + threadIdx.x;
    if (i < N) g_dinv[i] = rsqrtf(g_dinv[i]);
}

// ---------------- fp32 tiled GEMM: C[N,M] = A[N,K] * B[K,M] ----------------
__global__ void k_gemm(const float* __restrict__ A, const float* __restrict__ B,
                       float* __restrict__ C, int N, int K, int M) {
    __shared__ float As[16][68];   // [k][row], padded vs bank conflicts
    __shared__ float Bs[16][68];   // [k][col]
    int tid = threadIdx.x;         // 256 threads
    int tx = tid & 15, ty = tid >> 4;
    int row0 = blockIdx.y * 64, col0 = blockIdx.x * 64;
    float acc[4][4] = {};

    for (int k0 = 0; k0 < K; k0 += 16) {
        // load A tile: 64 rows x 16 k
        {
            int r  = tid >> 2;          // 0..63
            int c4 = (tid & 3) * 4;     // 0,4,8,12
            int gr = row0 + r;
#pragma unroll
            for (int i = 0; i < 4; i++) {
                int gk = k0 + c4 + i;
                As[c4 + i][r] = (gr < N && gk < K) ? A[(size_t)gr * K + gk] : 0.0f;
            }
        }
        // load B tile: 16 k x 64 cols
        {
            int lin = tid * 4;
            int r = lin >> 6;           // 0..15
            int c = lin & 63;
            int gk = k0 + r;
#pragma unroll
            for (int i = 0; i < 4; i++) {
                int gc = col0 + c + i;
                Bs[r][c + i] = (gk < K && gc < M) ? B[(size_t)gk * M + gc] : 0.0f;
            }
        }
        __syncthreads();
#pragma unroll
        for (int kk = 0; kk < 16; kk++) {
            float a[4], bb[4];
#pragma unroll
            for (int i = 0; i < 4; i++) a[i] = As[kk][ty * 4 + i];
#pragma unroll
            for (int j = 0; j < 4; j++) bb[j] = Bs[kk][tx * 4 + j];
#pragma unroll
            for (int i = 0; i < 4; i++)
#pragma unroll
                for (int j = 0; j < 4; j++)
                    acc[i][j] = fmaf(a[i], bb[j], acc[i][j]);
        }
        __syncthreads();
    }
#pragma unroll
    for (int i = 0; i < 4; i++) {
        int gr = row0 + ty * 4 + i;
        if (gr >= N) continue;
#pragma unroll
        for (int j = 0; j < 4; j++) {
            int gc = col0 + tx * 4 + j;
            if (gc < M) C[(size_t)gr * M + gc] = acc[i][j];
        }
    }
}

// ---------------- agg buffer init: bias + self-loop contribution ----------------
__global__ void k_init_agg(const float* __restrict__ h, const float* __restrict__ b,
                           float* __restrict__ agg, int N, int F) {
    size_t total = (size_t)N * F;
    size_t stride = (size_t)gridDim.x * blockDim.x;
    for (size_t i = (size_t)blockIdx.x * blockDim.x + threadIdx.x; i < total; i += stride) {
        int v = (int)(i / F);
        int f = (int)(i % F);
        float di = g_dinv[v];
        agg[i] = b[f] + h[i] * di * di;
    }
}

// ---------------- edge aggregation: agg[dst] += h[src] * dinv[src]*dinv[dst] ----
__global__ void k_edge_agg(const void* __restrict__ ei, int E, int F,
                           const float* __restrict__ h, float* __restrict__ agg) {
    int lane = threadIdx.x & 31;
    int warp = (blockIdx.x * blockDim.x + threadIdx.x) >> 5;
    int nw = (gridDim.x * blockDim.x) >> 5;
    for (int e = warp; e < E; e += nw) {
        int s, d;
        edge_sd(ei, e, E, s, d);
        float nrm = g_dinv[s] * g_dinv[d];
        const float* hr = h + (size_t)s * F;
        float* ar = agg + (size_t)d * F;
        for (int f = lane; f < F; f += 32)
            atomicAdd(&ar[f], hr[f] * nrm);
    }
}

// ---------------- BatchNorm(ReLU(x)) stats ----------------
__global__ void k_zero_stats() {
    int f = threadIdx.x;
    g_sum[f] = 0.0f;
    g_sumsq[f] = 0.0f;
}

__global__ void k_col_stats(const float* __restrict__ x, int N, int F) {
    int f = threadIdx.x;
    if (f >= F) return;
    int rpb = (N + gridDim.x - 1) / gridDim.x;
    int r0 = blockIdx.x * rpb;
    int r1 = min(N, r0 + rpb);
    float s = 0.0f, ss = 0.0f;
    for (int r = r0; r < r1; r++) {
        float v = fmaxf(x[(size_t)r * F + f], 0.0f);
        s += v;
        ss += v * v;
    }
    atomicAdd(&g_sum[f], s);
    atomicAdd(&g_sumsq[f], ss);
}

__global__ void k_fin_stats(int N, int F) {
    int f = threadIdx.x;
    if (f >= F) return;
    float mu = g_sum[f] / (float)N;
    float var = g_sumsq[f] / (float)N - mu * mu;
    g_mu[f] = mu;
    g_istd[f] = rsqrtf(fmaxf(var, 0.0f) + 1e-5f);
}

__global__ void k_bn(const float* __restrict__ x, const float* __restrict__ gam,
                     const float* __restrict__ bet, float* __restrict__ y, int N, int F) {
    size_t total = (size_t)N * F;
    size_t stride = (size_t)gridDim.x * blockDim.x;
    for (size_t i = (size_t)blockIdx.x * blockDim.x + threadIdx.x; i < total; i += stride) {
        int f = (int)(i % F);
        float v = fmaxf(x[i], 0.0f);
        y[i] = (v - g_mu[f]) * g_istd[f] * gam[f] + bet[f];
    }
}

// ---------------- final log_softmax (one warp per row; F <= 32) ----------------
__global__ void k_logsoftmax(const float* __restrict__ x, float* __restrict__ out,
                             int N, int F) {
    int warp = (blockIdx.x * blockDim.x + threadIdx.x) >> 5;
    int lane = threadIdx.x & 31;
    if (warp >= N) return;
    float v = (lane < F) ? x[(size_t)warp * F + lane] : -1e30f;
    float m = v;
#pragma unroll
    for (int o = 16; o; o >>= 1) m = fmaxf(m, __shfl_xor_sync(0xFFFFFFFFu, m, o));
    float e = (lane < F) ? expf(v - m) : 0.0f;
    float s = e;
#pragma unroll
    for (int o = 16; o; o >>= 1) s += __shfl_xor_sync(0xFFFFFFFFu, s, o);
    float lse = m + logf(s);
    if (lane < F) out[(size_t)warp * F + lane] = v - lse;
}

// ---------------- orchestration ----------------
extern "C" void kernel_launch(void* const* d_in, const int* in_sizes, int n_in,
                              void* d_out, int out_size) {
    const float* x = (const float*)d_in[0];
    const void* ei = d_in[1];
    const float *W[5], *b[5], *gam[4], *bet[4];
    for (int i = 0; i < 5; i++) {
        W[i] = (const float*)d_in[2 + 2 * i];
        b[i] = (const float*)d_in[3 + 2 * i];
    }
    for (int i = 0; i < 4; i++) {
        gam[i] = (const float*)d_in[12 + 2 * i];
        bet[i] = (const float*)d_in[13 + 2 * i];
    }
    int dims[6];
    for (int i = 0; i < 5; i++) dims[i + 1] = in_sizes[3 + 2 * i];  // bias sizes
    dims[0] = in_sizes[2] / dims[1];                                // F_in from W1
    int N = in_sizes[0] / dims[0];
    int E = in_sizes[1] / 2;

    float *bufA, *bufH, *bufG;
    cudaGetSymbolAddress((void**)&bufA, g_bufA);
    cudaGetSymbolAddress((void**)&bufH, g_bufH);
    cudaGetSymbolAddress((void**)&bufG, g_bufG);

    // preamble: dtype detect, degrees, dinv
    k_detect<<<1, 32>>>((const int*)ei);
    k_deg_init<<<(N + 255) / 256, 256>>>(N);
    k_deg<<<512, 256>>>(ei, E);
    k_dinv<<<(N + 255) / 256, 256>>>(N);

    const float* in = x;
    for (int l = 0; l < 5; l++) {
        int K = dims[l], M = dims[l + 1];
        dim3 grid((M + 63) / 64, (N + 63) / 64);
        k_gemm<<<grid, 256>>>(in, W[l], bufH, N, K, M);

        size_t tot = (size_t)N * M;
        size_t blk64 = (tot + 255) / 256;
        int blk = (int)(blk64 < 8192 ? blk64 : 8192);
        k_init_agg<<<blk, 256>>>(bufH, b[l], bufG, N, M);
        k_edge_agg<<<2048, 256>>>(ei, E, M, bufH, bufG);

        if (l < 4) {
            k_zero_stats<<<1, 256>>>();
            k_col_stats<<<128, 256>>>(bufG, N, M);
            k_fin_stats<<<1, 256>>>(N, M);
            k_bn<<<blk, 256>>>(bufG, gam[l], bet[l], bufA, N, M);
            in = bufA;
        } else {
            int warps_total = N;
            int blocks = (warps_total * 32 + 255) / 256;
            k_logsoftmax<<<blocks, 256>>>(bufG, (float*)d_out, N, M);
        }
    }
}